// round 17
// baseline (speedup 1.0000x reference)
#include <cuda_runtime.h>
#include <math.h>
#include <stdint.h>

#define BSZ    2048
#define DM     1024
#define HEADS  4
#define KD     256
#define HALFD  128
#define NK     512
#define KNN    32
#define ROWS   (BSZ*HEADS)   /* 8192 */

typedef unsigned long long u64;

// ---------------- scratch (static device globals; no allocation) ----------------
__device__ float g_q  [BSZ*DM];
__device__ float g_s  [ROWS*2*NK];
__device__ float g_tv [ROWS*2*KNN];
__device__ int   g_ti [ROWS*2*KNN];
__device__ float g_w  [ROWS*KNN];
__device__ int   g_idx[ROWS*KNN];

// ---------- packed f32x2 helpers ----------
__device__ __forceinline__ u64 pack_dup(float a) {
    u64 r;
    asm("mov.b64 %0, {%1, %1};" : "=l"(r) : "r"(__float_as_uint(a)));
    return r;
}
__device__ __forceinline__ void fma2(u64& d, u64 a, u64 b) {
    asm("fma.rn.f32x2 %0, %1, %2, %0;" : "+l"(d) : "l"(a), "l"(b));
}
__device__ __forceinline__ void unpack2(u64 v, float& lo, float& hi) {
    uint32_t l, h;
    asm("mov.b64 {%0, %1}, %2;" : "=r"(l), "=r"(h) : "l"(v));
    lo = __uint_as_float(l); hi = __uint_as_float(h);
}

// ---------- order-preserving float<->u32 map (no NaNs in this data) ----------
__device__ __forceinline__ uint32_t fkey(float f) {
    uint32_t u = __float_as_uint(f);
    return u ^ (uint32_t)(((int32_t)u >> 31) | 0x80000000);
}
__device__ __forceinline__ float funkey(uint32_t u) {
    u ^= (u & 0x80000000u) ? 0x80000000u : 0xFFFFFFFFu;
    return __uint_as_float(u);
}

// ============================================================================
// K1: q = x @ W^T + b  (M=2048, N=1024, K=1024, fp32)
// 128x128 tile, BK=16, 256 thr, 8x8 micro. A stored in smem PRE-DUPLICATED
// as f32x2 pairs (u64); B fragments loaded as raw ulonglong2 (packs free).
// Same FMA operands/order as R11 -> bit-identical result.
// Dynamic smem: As2 (u64[2*16*130]) + Bs (float[2*16*132]) = 50176 B.
// ============================================================================
#define K1_A_LD   130                      /* u64 row length (128 + pad2) */
#define K1_B_LD   132                      /* f32 row length */
#define K1_A_SZ   (2*16*K1_A_LD*8)         /* 33280 B */
#define K1_SMEM   (K1_A_SZ + 2*16*K1_B_LD*4)  /* 50176 B */

__global__ void __launch_bounds__(256) k_qproj(const float* __restrict__ x,
                                               const float* __restrict__ W,
                                               const float* __restrict__ bq) {
    extern __shared__ char sm[];
    u64*   As2 = (u64*)sm;                       // [2][16][130]
    float* Bs  = (float*)(sm + K1_A_SZ);         // [2][16][132]

    const int m0 = blockIdx.y * 128;
    const int n0 = blockIdx.x * 128;
    const int tid = threadIdx.x;
    const int tr = (tid >> 4) * 8;
    const int tc = (tid & 15) * 8;
    const int lrow = tid >> 2;          // 0..63
    const int lk4  = tid & 3;           // float4 index within BK=16

    const float* pa0 = x + (size_t)(m0 + lrow)      * DM + lk4 * 4;
    const float* pa1 = x + (size_t)(m0 + lrow + 64) * DM + lk4 * 4;
    const float* pb0 = W + (size_t)(n0 + lrow)      * DM + lk4 * 4;
    const float* pb1 = W + (size_t)(n0 + lrow + 64) * DM + lk4 * 4;

    u64 acc[8][4];
#pragma unroll
    for (int i = 0; i < 8; i++)
#pragma unroll
        for (int j = 0; j < 4; j++) acc[i][j] = 0ULL;

    float4 ra0 = *(const float4*)pa0;
    float4 ra1 = *(const float4*)pa1;
    float4 rb0 = *(const float4*)pb0;
    float4 rb1 = *(const float4*)pb1;
#define K1_STAGE_STORE(S)                                                     \
    do {                                                                      \
        u64*   A = As2 + (S) * (16 * K1_A_LD);                                \
        float* B = Bs  + (S) * (16 * K1_B_LD);                                \
        A[(lk4*4+0)*K1_A_LD + lrow]    = pack_dup(ra0.x);                     \
        A[(lk4*4+1)*K1_A_LD + lrow]    = pack_dup(ra0.y);                     \
        A[(lk4*4+2)*K1_A_LD + lrow]    = pack_dup(ra0.z);                     \
        A[(lk4*4+3)*K1_A_LD + lrow]    = pack_dup(ra0.w);                     \
        A[(lk4*4+0)*K1_A_LD + lrow+64] = pack_dup(ra1.x);                     \
        A[(lk4*4+1)*K1_A_LD + lrow+64] = pack_dup(ra1.y);                     \
        A[(lk4*4+2)*K1_A_LD + lrow+64] = pack_dup(ra1.z);                     \
        A[(lk4*4+3)*K1_A_LD + lrow+64] = pack_dup(ra1.w);                     \
        B[(lk4*4+0)*K1_B_LD + lrow]    = rb0.x;                               \
        B[(lk4*4+1)*K1_B_LD + lrow]    = rb0.y;                               \
        B[(lk4*4+2)*K1_B_LD + lrow]    = rb0.z;                               \
        B[(lk4*4+3)*K1_B_LD + lrow]    = rb0.w;                               \
        B[(lk4*4+0)*K1_B_LD + lrow+64] = rb1.x;                               \
        B[(lk4*4+1)*K1_B_LD + lrow+64] = rb1.y;                               \
        B[(lk4*4+2)*K1_B_LD + lrow+64] = rb1.z;                               \
        B[(lk4*4+3)*K1_B_LD + lrow+64] = rb1.w;                               \
    } while (0)

    K1_STAGE_STORE(0);
    __syncthreads();

    for (int c = 0; c < 64; c++) {
        const int cur = c & 1;
        if (c < 63) {
            const int k0 = (c + 1) * 16;
            ra0 = *(const float4*)(pa0 + k0);
            ra1 = *(const float4*)(pa1 + k0);
            rb0 = *(const float4*)(pb0 + k0);
            rb1 = *(const float4*)(pb1 + k0);
        }
        const u64*   Ac = As2 + cur * (16 * K1_A_LD);
        const float* Bc = Bs  + cur * (16 * K1_B_LD);
#pragma unroll
        for (int kk = 0; kk < 16; kk++) {
            const ulonglong2* pa2 = (const ulonglong2*)(Ac + kk * K1_A_LD + tr);
            const ulonglong2* pb2 = (const ulonglong2*)(Bc + kk * K1_B_LD + tc);
            ulonglong2 a01 = pa2[0], a23 = pa2[1], a45 = pa2[2], a67 = pa2[3];
            ulonglong2 b01 = pb2[0], b23 = pb2[1];
            u64 ad[8] = {a01.x, a01.y, a23.x, a23.y, a45.x, a45.y, a67.x, a67.y};
            u64 bp[4] = {b01.x, b01.y, b23.x, b23.y};
#pragma unroll
            for (int i = 0; i < 8; i++)
#pragma unroll
                for (int j = 0; j < 4; j++) fma2(acc[i][j], ad[i], bp[j]);
        }
        if (c < 63) {
            const int nxt = 1 - cur;
            K1_STAGE_STORE(nxt);
        }
        __syncthreads();
    }

#pragma unroll
    for (int i = 0; i < 8; i++) {
        float* op = g_q + (size_t)(m0 + tr + i) * DM + n0 + tc;
        float r[8];
#pragma unroll
        for (int j = 0; j < 4; j++) unpack2(acc[i][j], r[2*j], r[2*j+1]);
#pragma unroll
        for (int j = 0; j < 8; j++) op[j] = r[j] + bq[n0 + tc + j];
    }
}

// ============================================================================
// K2: s1 = q1 @ keys^T, s2 = q2 @ keys^T  packed as S[8192][1024]
// 128x64 tile, BK=16 (8 chunks), 256 thr, 8x4 micro. Same dup-A / raw-B
// pack elimination. Static smem: As2 33280 + Bs 8704 = 41984 B.
// ============================================================================
__global__ void __launch_bounds__(256) k_scores(const float* __restrict__ keys) {
    __shared__ u64   As2[2][16][130];
    __shared__ float Bs [2][16][68];
    const int r0 = blockIdx.y * 128;
    const int j0 = blockIdx.x * 64;
    const int half = (j0 >= NK) ? 1 : 0;
    const int jb = j0 - half * NK;
    const int tid = threadIdx.x;
    const int tr = (tid >> 4) * 8;
    const int tc = (tid & 15) * 4;
    const int lrow = tid >> 2;          // 0..63
    const int lk4  = tid & 3;

    const float* pa0 = g_q + (size_t)(r0 + lrow)      * KD + half * HALFD + lk4 * 4;
    const float* pa1 = g_q + (size_t)(r0 + lrow + 64) * KD + half * HALFD + lk4 * 4;
    const float* pb0 = keys + (size_t)(jb + lrow) * HALFD + lk4 * 4;

    u64 acc[8][2];
#pragma unroll
    for (int i = 0; i < 8; i++) { acc[i][0] = 0ULL; acc[i][1] = 0ULL; }

    float4 ra0 = *(const float4*)pa0;
    float4 ra1 = *(const float4*)pa1;
    float4 rb0 = *(const float4*)pb0;
#define K2_STAGE_STORE(S)                                                     \
    do {                                                                      \
        As2[S][lk4*4+0][lrow]    = pack_dup(ra0.x);                           \
        As2[S][lk4*4+1][lrow]    = pack_dup(ra0.y);                           \
        As2[S][lk4*4+2][lrow]    = pack_dup(ra0.z);                           \
        As2[S][lk4*4+3][lrow]    = pack_dup(ra0.w);                           \
        As2[S][lk4*4+0][lrow+64] = pack_dup(ra1.x);                           \
        As2[S][lk4*4+1][lrow+64] = pack_dup(ra1.y);                           \
        As2[S][lk4*4+2][lrow+64] = pack_dup(ra1.z);                           \
        As2[S][lk4*4+3][lrow+64] = pack_dup(ra1.w);                           \
        Bs [S][lk4*4+0][lrow]    = rb0.x;                                     \
        Bs [S][lk4*4+1][lrow]    = rb0.y;                                     \
        Bs [S][lk4*4+2][lrow]    = rb0.z;                                     \
        Bs [S][lk4*4+3][lrow]    = rb0.w;                                     \
    } while (0)

    K2_STAGE_STORE(0);
    __syncthreads();

    for (int c = 0; c < 8; c++) {
        const int cur = c & 1;
        if (c < 7) {
            const int k0 = (c + 1) * 16;
            ra0 = *(const float4*)(pa0 + k0);
            ra1 = *(const float4*)(pa1 + k0);
            rb0 = *(const float4*)(pb0 + k0);
        }
#pragma unroll
        for (int kk = 0; kk < 16; kk++) {
            const ulonglong2* pa2 = (const ulonglong2*)(&As2[cur][kk][tr]);
            const ulonglong2* pb2 = (const ulonglong2*)(&Bs[cur][kk][tc]);
            ulonglong2 a01 = pa2[0], a23 = pa2[1], a45 = pa2[2], a67 = pa2[3];
            ulonglong2 bb  = pb2[0];
            u64 ad[8] = {a01.x, a01.y, a23.x, a23.y, a45.x, a45.y, a67.x, a67.y};
#pragma unroll
            for (int i = 0; i < 8; i++) {
                fma2(acc[i][0], ad[i], bb.x);
                fma2(acc[i][1], ad[i], bb.y);
            }
        }
        if (c < 7) {
            const int nxt = 1 - cur;
            K2_STAGE_STORE(nxt);
        }
        __syncthreads();
    }
#pragma unroll
    for (int i = 0; i < 8; i++) {
        float4 v;
        unpack2(acc[i][0], v.x, v.y);
        unpack2(acc[i][1], v.z, v.w);
        *(float4*)(g_s + (size_t)(r0 + tr + i) * 1024 + j0 + tc) = v;
    }
}

// ============================================================================
// K3: stage-1 top-32 (R11 committed config)
// ============================================================================
__global__ void __launch_bounds__(256) k_topk1() {
    __shared__ uint32_t su[8][16][32];
    __shared__ short    sg[8][16][32];
    const int wid  = threadIdx.x >> 5;
    const int lane = threadIdx.x & 31;
    const int task = blockIdx.x * 8 + wid;
    const int r = task >> 1;
    const int half = task & 1;
    const float* s = g_s + (size_t)r * 1024 + half * NK;

    uint32_t uu[16]; int tt[16];
#pragma unroll
    for (int t = 0; t < 16; t++) { uu[t] = fkey(s[t * 32 + lane]); tt[t] = t; }

#pragma unroll
    for (int p = 1; p < 16; p <<= 1) {
#pragma unroll
        for (int k = p; k >= 1; k >>= 1) {
#pragma unroll
            for (int j = k & (p - 1); j + k < 16; j += 2 * k) {
#pragma unroll
                for (int i = 0; i < k; i++) {
                    if (((i + j) / (2 * p)) == ((i + j + k) / (2 * p))) {
                        const int xa = i + j, xb = i + j + k;
                        bool sw = (uu[xb] > uu[xa]) ||
                                  (uu[xb] == uu[xa] && tt[xb] < tt[xa]);
                        uint32_t fu = sw ? uu[xb] : uu[xa];
                        uint32_t gu = sw ? uu[xa] : uu[xb];
                        int      ft = sw ? tt[xb] : tt[xa];
                        int      gt = sw ? tt[xa] : tt[xb];
                        uu[xa] = fu; uu[xb] = gu; tt[xa] = ft; tt[xb] = gt;
                    }
                }
            }
        }
    }

#pragma unroll
    for (int t = 0; t < 16; t++) {
        su[wid][t][lane] = uu[t];
        sg[wid][t][lane] = (short)(tt[t] * 32 + lane);
    }
    __syncwarp();

    int p = 0;
    uint32_t cu  = su[wid][0][lane];
    uint32_t cgi = (uint32_t)sg[wid][0][lane];
    uint32_t outu = 0; int outi = 0;

    for (int sel = 0; sel < 32; sel++) {
        const uint32_t m = __reduce_max_sync(0xffffffffu, cu);
        const uint32_t cand = (cu == m) ? cgi : 0xFFFFFFFFu;
        const uint32_t g = __reduce_min_sync(0xffffffffu, cand);
        if (lane == sel) { outu = m; outi = (int)g; }
        if (cgi == g) {
            p++;
            if (p < 16) {
                cu  = su[wid][p][lane];
                cgi = (uint32_t)sg[wid][p][lane];
            } else {
                cu  = 0u;
                cgi = 1024u + lane;
            }
        }
    }
    g_tv[(size_t)task * 32 + lane] = funkey(outu);
    g_ti[(size_t)task * 32 + lane] = outi;
}

// ============================================================================
// K4: combine + softmax (R11 committed config)
// ============================================================================
__global__ void __launch_bounds__(256) k_combine() {
    const int wid  = threadIdx.x >> 5;
    const int lane = threadIdx.x & 31;
    const int r = blockIdx.x * 8 + wid;

    const float v1 = g_tv[(size_t)(r * 2 + 0) * 32 + lane];
    const int   i1 = g_ti[(size_t)(r * 2 + 0) * 32 + lane];
    const float v2 = g_tv[(size_t)(r * 2 + 1) * 32 + lane];
    const int   i2 = g_ti[(size_t)(r * 2 + 1) * 32 + lane];

    int p = 0;
    uint32_t cu = fkey(v1 + __shfl_sync(0xffffffffu, v2, 0));
    uint32_t fi = (uint32_t)(lane * 32);
    uint32_t myu = 0; int myidx = 0;

    for (int sel = 0; sel < 32; sel++) {
        const uint32_t m = __reduce_max_sync(0xffffffffu, cu);
        const uint32_t cand = (cu == m) ? fi : 0xFFFFFFFFu;
        const uint32_t g = __reduce_min_sync(0xffffffffu, cand);
        const int a = (int)(g >> 5), b = (int)(g & 31);
        const int vid = __shfl_sync(0xffffffffu, i1, a) * NK +
                        __shfl_sync(0xffffffffu, i2, b);
        if (lane == sel) { myu = m; myidx = vid; }

        const bool adv = (fi == g);
        const int pn = p + (adv ? 1 : 0);
        const float s2p = __shfl_sync(0xffffffffu, v2, pn & 31);  // uniform shfl
        if (adv) {
            p = pn;
            if (p < 32) {
                cu = fkey(v1 + s2p);
                fi = (uint32_t)(lane * 32 + p);
            } else {
                cu = 0u;
                fi = 2048u + lane;
            }
        }
    }

    const float myval = funkey(myu);
    const float mx = __shfl_sync(0xffffffffu, myval, 0);
    float e = expf(myval - mx);
    float sum = e;
#pragma unroll
    for (int off = 16; off > 0; off >>= 1)
        sum += __shfl_xor_sync(0xffffffffu, sum, off);
    g_w  [(size_t)r * 32 + lane] = e / sum;
    g_idx[(size_t)r * 32 + lane] = myidx;
}

// ============================================================================
// K5: out[b,:] = sum_{k=0..127} w[b,k] * values[idx[b,k], :]  (R11 config)
// ============================================================================
__global__ void __launch_bounds__(256) k_gather(const float* __restrict__ values,
                                                float* __restrict__ out) {
    const int b = blockIdx.x;
    const int tid = threadIdx.x;
    __shared__ float sw[128];
    __shared__ int   si[128];
    if (tid < 128) {
        sw[tid] = g_w  [(size_t)b * 128 + tid];
        si[tid] = g_idx[(size_t)b * 128 + tid];
    }
    __syncthreads();

    float4 acc = make_float4(0.f, 0.f, 0.f, 0.f);
#pragma unroll 8
    for (int k = 0; k < 128; k++) {
        const float4 v = ((const float4*)(values + (size_t)si[k] * DM))[tid];
        const float w = sw[k];
        acc.x += w * v.x; acc.y += w * v.y;
        acc.z += w * v.z; acc.w += w * v.w;
    }
    ((float4*)out)[(size_t)b * 256 + tid] = acc;
}

// ============================================================================
extern "C" void kernel_launch(void* const* d_in, const int* in_sizes, int n_in,
                              void* d_out, int out_size) {
    const float* x      = (const float*)d_in[0];
    const float* W      = (const float*)d_in[1];
    const float* bq     = (const float*)d_in[2];
    const float* keys   = (const float*)d_in[3];
    const float* values = (const float*)d_in[4];
    float* out = (float*)d_out;

    cudaFuncSetAttribute(k_qproj, cudaFuncAttributeMaxDynamicSharedMemorySize,
                         K1_SMEM);

    k_qproj  <<<dim3(DM / 128, BSZ / 128), 256, K1_SMEM>>>(x, W, bq);
    k_scores <<<dim3(1024 / 64, ROWS / 128), 256>>>(keys);
    k_topk1  <<<(ROWS * 2) / 8, 256>>>();
    k_combine<<<ROWS / 8, 256>>>();
    k_gather <<<BSZ, 256>>>(values, out);
}